// round 14
// baseline (speedup 1.0000x reference)
#include <cuda_runtime.h>
#include <cuda_fp16.h>
#include <cstdint>
#include <math.h>

// ================= Problem constants =================
#define Bc 8
#define Ntok 4096
#define Cch 512
#define NHI 1024

typedef __half fp16;

// ================= Scratch =================
__device__ float g_out_hi[Bc * NHI * Cch];
__device__ float g_qkv_lo[(size_t)Bc * 1024 * 4 * 1536];
__device__ float g_sum[(size_t)Bc * Ntok * Cch];

__device__ fp16 g_xhih[Bc * NHI * Cch], g_xhil[Bc * NHI * Cch];
__device__ fp16 g_Wqh[1536 * 512];
__device__ fp16 g_qh[(size_t)Bc * NHI * 1536], g_ql[(size_t)Bc * NHI * 1536];
__device__ fp16 g_winh[(size_t)Bc * Ntok * Cch], g_winl[(size_t)Bc * Ntok * Cch];
__device__ fp16 g_Wloh[1536 * 512];
__device__ fp16 g_sumh[(size_t)Bc * Ntok * Cch], g_suml[(size_t)Bc * Ntok * Cch];
__device__ fp16 g_Wph[512 * 512];

// ================= helpers =================
__device__ __forceinline__ uint32_t smem_to_u32(const void* p) {
    uint32_t a;
    asm("{ .reg .u64 t; cvta.to.shared.u64 t, %1; cvt.u32.u64 %0, t; }" : "=r"(a) : "l"(p));
    return a;
}

__device__ __forceinline__ void cp16(uint32_t s, const void* g) {
    asm volatile("cp.async.cg.shared.global [%0], [%1], 16;" :: "r"(s), "l"(g) : "memory");
}
__device__ __forceinline__ void cp_commit() {
    asm volatile("cp.async.commit_group;" ::: "memory");
}
template <int N>
__device__ __forceinline__ void cp_wait() {
    asm volatile("cp.async.wait_group %0;" :: "n"(N) : "memory");
}

__device__ __forceinline__ void ldm4(uint32_t* r, uint32_t addr) {
    asm volatile("ldmatrix.sync.aligned.m8n8.x4.shared.b16 {%0,%1,%2,%3}, [%4];"
        : "=r"(r[0]), "=r"(r[1]), "=r"(r[2]), "=r"(r[3]) : "r"(addr));
}
__device__ __forceinline__ void ldm4t(uint32_t* r, uint32_t addr) {
    asm volatile("ldmatrix.sync.aligned.m8n8.x4.trans.shared.b16 {%0,%1,%2,%3}, [%4];"
        : "=r"(r[0]), "=r"(r[1]), "=r"(r[2]), "=r"(r[3]) : "r"(addr));
}

__device__ __forceinline__ void mma16816(float* c, const uint32_t* a, uint32_t b0, uint32_t b1) {
    asm volatile(
        "mma.sync.aligned.m16n8k16.row.col.f32.f16.f16.f32 "
        "{%0,%1,%2,%3}, {%4,%5,%6,%7}, {%8,%9}, {%0,%1,%2,%3};"
        : "+f"(c[0]), "+f"(c[1]), "+f"(c[2]), "+f"(c[3])
        : "r"(a[0]), "r"(a[1]), "r"(a[2]), "r"(a[3]), "r"(b0), "r"(b1));
}

__device__ __forceinline__ void psplit2(float x, float y, uint32_t& hp, uint32_t& lp) {
    fp16 hx = __float2half_rn(x), hy = __float2half_rn(y);
    fp16 lx = __float2half_rn(x - __half2float(hx));
    fp16 ly = __float2half_rn(y - __half2float(hy));
    hp = (uint32_t)*(uint16_t*)&hx | ((uint32_t)*(uint16_t*)&hy << 16);
    lp = (uint32_t)*(uint16_t*)&lx | ((uint32_t)*(uint16_t*)&ly << 16);
}

// ================= split-fp16 2-pass GEMM via mma.sync =================
// C = alpha * (Ah+Al) @ Bh^T (+bias). A split fp16, B single fp16.
// OUTMODE: 0 = fp32 C, 1 = fp32 C + bias, 2 = split fp16 (Ch, Cl)
template <int NT, int OUTMODE>
__global__ void __launch_bounds__(NT == 128 ? 256 : 128) mma_gemm(
    const fp16* __restrict__ Ah, const fp16* __restrict__ Al, int lda, long long sAb, long long sAh,
    const fp16* __restrict__ Bh, int ldb, long long sBb, long long sBh,
    float* __restrict__ C, fp16* __restrict__ Ch, fp16* __restrict__ Cl,
    int ldc, long long sCb, long long sCh,
    const float* __restrict__ bias, int K, float alpha, int hdiv)
{
    constexpr int THREADS = (NT == 128) ? 256 : 128;
    constexpr int NWC = NT / 32;
    constexpr int BBYTES = NT * 128;        // single-precision-fp16 B tile
    constexpr int STAGE = 32768 + BBYTES;

    extern __shared__ __align__(1024) char smem[];
    uint32_t sb = smem_to_u32(smem);
    int tid = threadIdx.x, wid = tid >> 5, lane = tid & 31;
    int wr = wid / NWC, wc = wid % NWC;

    int z = blockIdx.z, zb = z / hdiv, zh = z - zb * hdiv;
    long long offA = zb * sAb + zh * sAh;
    long long offB = zb * sBb + zh * sBh;
    Ah += offA; Al += offA; Bh += offB;
    long long offC = zb * sCb + zh * sCh;
    int bm = blockIdx.y * 128, bn = blockIdx.x * NT;

    float acc[4][4][4];
#pragma unroll
    for (int i = 0; i < 4; i++)
#pragma unroll
        for (int j = 0; j < 4; j++)
#pragma unroll
            for (int t = 0; t < 4; t++) acc[i][j][t] = 0.f;

    int NC = K >> 6;

    auto issue = [&](int c) {
        int s = c & 1;
        int k0 = c * 64;
        uint32_t sbase = sb + s * STAGE;
#pragma unroll
        for (int i = 0; i < 1024 / THREADS; i++) {
            int idx = tid + i * THREADS;
            int row = idx >> 3, c16 = idx & 7;
            uint32_t d = (uint32_t)(row * 128 + ((c16 ^ (row & 7)) << 4));
            size_t go = (size_t)(bm + row) * lda + k0 + c16 * 8;
            cp16(sbase + d, Ah + go);
            cp16(sbase + 16384 + d, Al + go);
        }
#pragma unroll
        for (int i = 0; i < (NT * 8) / THREADS; i++) {
            int idx = tid + i * THREADS;
            int row = idx >> 3, c16 = idx & 7;
            uint32_t d = (uint32_t)(row * 128 + ((c16 ^ (row & 7)) << 4));
            size_t go = (size_t)(bn + row) * ldb + k0 + c16 * 8;
            cp16(sbase + 32768 + d, Bh + go);
        }
        cp_commit();
    };

    issue(0);

    for (int c = 0; c < NC; c++) {
        if (c + 1 < NC) { issue(c + 1); cp_wait<1>(); }
        else            { cp_wait<0>(); }
        __syncthreads();

        uint32_t Ab = sb + (c & 1) * STAGE;
        uint32_t Bb = Ab + 32768;
#pragma unroll
        for (int ks = 0; ks < 4; ks++) {
            uint32_t ah[4][4], al[4][4];
#pragma unroll
            for (int i = 0; i < 4; i++) {
                int row = wr * 64 + i * 16 + (lane & 15);
                int c16 = ks * 2 + (lane >> 4);
                uint32_t ad = (uint32_t)(row * 128 + ((c16 ^ (row & 7)) << 4));
                ldm4(ah[i], Ab + ad);
                ldm4(al[i], Ab + 16384 + ad);
            }
            uint32_t bh[8];
#pragma unroll
            for (int j2 = 0; j2 < 2; j2++) {
                int nrow = wc * 32 + j2 * 16 + ((lane >> 4) << 3) + (lane & 7);
                int c16 = ks * 2 + ((lane >> 3) & 1);
                uint32_t bd = (uint32_t)(nrow * 128 + ((c16 ^ (nrow & 7)) << 4));
                ldm4(&bh[j2 * 4], Bb + bd);
            }
#pragma unroll
            for (int i = 0; i < 4; i++)
#pragma unroll
                for (int j = 0; j < 4; j++) {
                    mma16816(acc[i][j], ah[i], bh[j * 2], bh[j * 2 + 1]);
                    mma16816(acc[i][j], al[i], bh[j * 2], bh[j * 2 + 1]);
                }
        }
        __syncthreads();
    }

    int r = lane >> 2, cp2 = (lane & 3) * 2;
#pragma unroll
    for (int i = 0; i < 4; i++) {
        int row = bm + wr * 64 + i * 16 + r;
#pragma unroll
        for (int j = 0; j < 4; j++) {
            int col = bn + wc * 32 + j * 8 + cp2;
            float2 v0, v1;
            v0.x = acc[i][j][0] * alpha; v0.y = acc[i][j][1] * alpha;
            v1.x = acc[i][j][2] * alpha; v1.y = acc[i][j][3] * alpha;
            if (OUTMODE == 1) {
                float b0 = bias[col], b1 = bias[col + 1];
                v0.x += b0; v0.y += b1; v1.x += b0; v1.y += b1;
            }
            if (OUTMODE == 2) {
                uint32_t hp, lp;
                psplit2(v0.x, v0.y, hp, lp);
                *(uint32_t*)&Ch[(offC + (size_t)row * ldc + col)] = hp;
                *(uint32_t*)&Cl[(offC + (size_t)row * ldc + col)] = lp;
                psplit2(v1.x, v1.y, hp, lp);
                *(uint32_t*)&Ch[(offC + (size_t)(row + 8) * ldc + col)] = hp;
                *(uint32_t*)&Cl[(offC + (size_t)(row + 8) * ldc + col)] = lp;
            } else {
                *(float2*)&C[offC + (size_t)row * ldc + col] = v0;
                *(float2*)&C[offC + (size_t)(row + 8) * ldc + col] = v1;
            }
        }
    }
}

// ================= FlashAttention-2 hi-branch (fp16 2-pass) =================
// Q split (qh/ql), K and V single fp16 (high parts). out_hi fp32.
__global__ void __launch_bounds__(128) flash_hi(
    const fp16* __restrict__ Qh, const fp16* __restrict__ Ql, float* __restrict__ outhi)
{
    extern __shared__ __align__(1024) char smem[];
    uint32_t sb = smem_to_u32(smem);
    const uint32_t sQh = sb, sQl = sb + 16384;
    int tid = threadIdx.x, wid = tid >> 5, lane = tid & 31;
    int mtile = blockIdx.x, bh = blockIdx.y;
    int b = bh >> 3, h = bh & 7;

    size_t qbase = ((size_t)(b * 1024) + mtile * 128) * 1536 + h * 64;
#pragma unroll
    for (int i = 0; i < 8; i++) {
        int idx = tid + i * 128;
        int row = idx >> 3, c16 = idx & 7;
        uint32_t d = (uint32_t)(row * 128 + ((c16 ^ (row & 7)) << 4));
        size_t go = qbase + (size_t)row * 1536 + c16 * 8;
        cp16(sQh + d, Qh + go);
        cp16(sQl + d, Ql + go);
    }
    cp_commit();

    auto issueKV = [&](int t) {
        uint32_t kb = sb + 32768 + (t & 1) * 16384;
        size_t kbase = ((size_t)(b * 1024) + t * 64) * 1536 + 512 + h * 64;
#pragma unroll
        for (int i = 0; i < 4; i++) {
            int idx = tid + i * 128;
            int row = idx >> 3, c16 = idx & 7;
            uint32_t d = (uint32_t)(row * 128 + ((c16 ^ (row & 7)) << 4));
            size_t go = kbase + (size_t)row * 1536 + c16 * 8;
            cp16(kb + d, Qh + go);            // Kh
            cp16(kb + 8192 + d, Qh + go + 512); // Vh
        }
        cp_commit();
    };
    issueKV(0);
    issueKV(1);

    int rbase = wid * 32;
    float o[2][8][4];
    float mrow[2][2], lrow[2][2];
#pragma unroll
    for (int mi = 0; mi < 2; mi++) {
#pragma unroll
        for (int j = 0; j < 8; j++)
#pragma unroll
            for (int e = 0; e < 4; e++) o[mi][j][e] = 0.f;
        mrow[mi][0] = -INFINITY; mrow[mi][1] = -INFINITY;
        lrow[mi][0] = 0.f; lrow[mi][1] = 0.f;
    }

    for (int t = 0; t < 16; t++) {
        if (t < 15) cp_wait<1>(); else cp_wait<0>();
        __syncthreads();
        uint32_t kb = sb + 32768 + (t & 1) * 16384;

        float s[2][8][4];
#pragma unroll
        for (int mi = 0; mi < 2; mi++)
#pragma unroll
            for (int j = 0; j < 8; j++)
#pragma unroll
                for (int e = 0; e < 4; e++) s[mi][j][e] = 0.f;

#pragma unroll
        for (int kd = 0; kd < 4; kd++) {
            uint32_t aqh[2][4], aql[2][4];
#pragma unroll
            for (int mi = 0; mi < 2; mi++) {
                int row = rbase + mi * 16 + (lane & 15);
                int c16 = kd * 2 + (lane >> 4);
                uint32_t ad = (uint32_t)(row * 128 + ((c16 ^ (row & 7)) << 4));
                ldm4(aqh[mi], sQh + ad);
                ldm4(aql[mi], sQl + ad);
            }
            uint32_t bkh[16];
#pragma unroll
            for (int j2 = 0; j2 < 4; j2++) {
                int nrow = j2 * 16 + ((lane >> 4) << 3) + (lane & 7);
                int c16 = kd * 2 + ((lane >> 3) & 1);
                uint32_t bd = (uint32_t)(nrow * 128 + ((c16 ^ (nrow & 7)) << 4));
                ldm4(&bkh[j2 * 4], kb + bd);
            }
#pragma unroll
            for (int mi = 0; mi < 2; mi++)
#pragma unroll
                for (int j = 0; j < 8; j++) {
                    mma16816(s[mi][j], aqh[mi], bkh[j * 2], bkh[j * 2 + 1]);
                    mma16816(s[mi][j], aql[mi], bkh[j * 2], bkh[j * 2 + 1]);
                }
        }

#pragma unroll
        for (int mi = 0; mi < 2; mi++)
#pragma unroll
            for (int j = 0; j < 8; j++)
#pragma unroll
                for (int e = 0; e < 4; e++) s[mi][j][e] *= 0.125f;

#pragma unroll
        for (int mi = 0; mi < 2; mi++)
#pragma unroll
            for (int hf = 0; hf < 2; hf++) {
                float tm = -INFINITY;
#pragma unroll
                for (int j = 0; j < 8; j++)
                    tm = fmaxf(tm, fmaxf(s[mi][j][hf * 2], s[mi][j][hf * 2 + 1]));
                tm = fmaxf(tm, __shfl_xor_sync(0xffffffffu, tm, 1));
                tm = fmaxf(tm, __shfl_xor_sync(0xffffffffu, tm, 2));
                float mnew = fmaxf(mrow[mi][hf], tm);
                float corr = __expf(mrow[mi][hf] - mnew);
                mrow[mi][hf] = mnew;
                float rs = 0.f;
#pragma unroll
                for (int j = 0; j < 8; j++) {
                    float p0 = __expf(s[mi][j][hf * 2] - mnew);
                    float p1 = __expf(s[mi][j][hf * 2 + 1] - mnew);
                    s[mi][j][hf * 2] = p0; s[mi][j][hf * 2 + 1] = p1;
                    rs += p0 + p1;
                }
                rs += __shfl_xor_sync(0xffffffffu, rs, 1);
                rs += __shfl_xor_sync(0xffffffffu, rs, 2);
                lrow[mi][hf] = lrow[mi][hf] * corr + rs;
#pragma unroll
                for (int j = 0; j < 8; j++) {
                    o[mi][j][hf * 2] *= corr; o[mi][j][hf * 2 + 1] *= corr;
                }
            }

#pragma unroll
        for (int tt = 0; tt < 4; tt++) {
            uint32_t aph[2][4], apl[2][4];
#pragma unroll
            for (int mi = 0; mi < 2; mi++) {
                psplit2(s[mi][2 * tt][0], s[mi][2 * tt][1], aph[mi][0], apl[mi][0]);
                psplit2(s[mi][2 * tt][2], s[mi][2 * tt][3], aph[mi][1], apl[mi][1]);
                psplit2(s[mi][2 * tt + 1][0], s[mi][2 * tt + 1][1], aph[mi][2], apl[mi][2]);
                psplit2(s[mi][2 * tt + 1][2], s[mi][2 * tt + 1][3], aph[mi][3], apl[mi][3]);
            }
            uint32_t bvh[16];
#pragma unroll
            for (int j2 = 0; j2 < 4; j2++) {
                int vrow = tt * 16 + ((lane >> 3) & 1) * 8 + (lane & 7);
                int c16 = j2 * 2 + (lane >> 4);
                uint32_t vd = (uint32_t)(vrow * 128 + ((c16 ^ (vrow & 7)) << 4));
                ldm4t(&bvh[j2 * 4], kb + 8192 + vd);
            }
#pragma unroll
            for (int mi = 0; mi < 2; mi++)
#pragma unroll
                for (int j = 0; j < 8; j++) {
                    mma16816(o[mi][j], aph[mi], bvh[j * 2], bvh[j * 2 + 1]);
                    mma16816(o[mi][j], apl[mi], bvh[j * 2], bvh[j * 2 + 1]);
                }
        }
        __syncthreads();
        if (t + 2 < 16) issueKV(t + 2);
    }

    size_t obase = ((size_t)(b * 1024) + mtile * 128) * 512 + h * 64;
    int r = lane >> 2, c2 = (lane & 3) * 2;
#pragma unroll
    for (int mi = 0; mi < 2; mi++)
#pragma unroll
        for (int hf = 0; hf < 2; hf++) {
            float inv = 1.f / lrow[mi][hf];
            int grow = rbase + mi * 16 + hf * 8 + r;
#pragma unroll
            for (int j = 0; j < 8; j++) {
                float2 v;
                v.x = o[mi][j][hf * 2] * inv;
                v.y = o[mi][j][hf * 2 + 1] * inv;
                *(float2*)&outhi[obase + (size_t)grow * 512 + j * 8 + c2] = v;
            }
        }
}

// ================= prep kernels =================
__device__ __forceinline__ void split4(float4 v, fp16* h, fp16* l, size_t base)
{
    float a[4] = { v.x, v.y, v.z, v.w };
    fp16 hh[4], ll[4];
#pragma unroll
    for (int i = 0; i < 4; i++) {
        hh[i] = __float2half_rn(a[i]);
        ll[i] = __float2half_rn(a[i] - __half2float(hh[i]));
    }
    *(uint2*)(h + base) = *(uint2*)hh;
    *(uint2*)(l + base) = *(uint2*)ll;
}

// fp32 -> single fp16
__global__ void conv_single(const float4* __restrict__ src, fp16* __restrict__ h, int n4)
{
    int gid = blockIdx.x * 256 + threadIdx.x;
    if (gid >= n4) return;
    float4 v = src[gid];
    fp16 hh[4] = { __float2half_rn(v.x), __float2half_rn(v.y),
                   __float2half_rn(v.z), __float2half_rn(v.w) };
    *(uint2*)(h + (size_t)gid * 4) = *(uint2*)hh;
}

__global__ void pool_split(const float* __restrict__ x)
{
    int gid = blockIdx.x * 256 + threadIdx.x;
    int c4 = gid & 127;
    int hw = (gid >> 7) & 1023;
    int b = gid >> 17;
    int wh = hw >> 5, ww = hw & 31;
    int n0 = (wh * 2) * 64 + ww * 2;
    const float4* xb = (const float4*)(x + (size_t)b * Ntok * Cch);
    float4 a = xb[(size_t)n0 * 128 + c4];
    float4 bv = xb[(size_t)(n0 + 1) * 128 + c4];
    float4 c = xb[(size_t)(n0 + 64) * 128 + c4];
    float4 d = xb[(size_t)(n0 + 65) * 128 + c4];
    float4 o;
    o.x = (a.x + bv.x + c.x + d.x) * 0.25f;
    o.y = (a.y + bv.y + c.y + d.y) * 0.25f;
    o.z = (a.z + bv.z + c.z + d.z) * 0.25f;
    o.w = (a.w + bv.w + c.w + d.w) * 0.25f;
    split4(o, g_xhih, g_xhil, (size_t)gid * 4);
}

__global__ void gather_win_split(const float* __restrict__ x)
{
    int gid = blockIdx.x * 256 + threadIdx.x;
    int k4 = gid & 127;
    int m = gid >> 7;
    int t = m & 3, w = (m >> 2) & 1023, b = m >> 12;
    int kp = k4 * 4;
    int p = kp >> 7, q = kp & 127;
    int wh = w >> 5, ww = w & 31;
    int i = p >> 1, j = p & 1;
    int n = (wh * 2 + i) * 64 + ww * 2 + j;
    float4 v = *(const float4*)(x + ((size_t)b * Ntok + n) * Cch + t * 128 + q);
    split4(v, g_winh, g_winl, (size_t)gid * 4);
}

__global__ void permw_single(const float* __restrict__ W)
{
    int gid = blockIdx.x * 256 + threadIdx.x;
    if (gid >= 1536 * 512) return;
    int kp = gid & 511, j = gid >> 9;
    int p = kp >> 7, q = kp & 127;
    g_Wloh[gid] = __float2half_rn(W[j * 512 + q * 4 + p]);
}

__device__ __forceinline__ void up_weights(int y, int& ia, int& ib, float& wa, float& wb)
{
    int m = y >> 1;
    if ((y & 1) == 0) { ia = m - 1 < 0 ? 0 : m - 1; ib = m; wa = 0.25f; wb = 0.75f; }
    else { ia = m; ib = m + 1 > 31 ? 31 : m + 1; wa = 0.75f; wb = 0.25f; }
}

__global__ void upsample_kernel()
{
    int gid = blockIdx.x * 256 + threadIdx.x;
    int c4 = gid & 127;
    int n = (gid >> 7) & 4095;
    int b = gid >> 19;
    int y = n >> 6, x = n & 63;
    int ya, yb2; float wya, wyb;
    int xa, xb2; float wxa, wxb;
    up_weights(y, ya, yb2, wya, wyb);
    up_weights(x, xa, xb2, wxa, wxb);
    const float4* src = (const float4*)(g_out_hi + (size_t)b * NHI * Cch);
    float4 vaa = src[(size_t)(ya * 32 + xa) * 128 + c4];
    float4 vab = src[(size_t)(ya * 32 + xb2) * 128 + c4];
    float4 vba = src[(size_t)(yb2 * 32 + xa) * 128 + c4];
    float4 vbb = src[(size_t)(yb2 * 32 + xb2) * 128 + c4];
    float waa = wya * wxa, wab = wya * wxb, wba = wyb * wxa, wbb = wyb * wxb;
    float4 o;
    o.x = waa * vaa.x + wab * vab.x + wba * vba.x + wbb * vbb.x;
    o.y = waa * vaa.y + wab * vab.y + wba * vba.y + wbb * vbb.y;
    o.z = waa * vaa.z + wab * vab.z + wba * vba.z + wbb * vbb.z;
    o.w = waa * vaa.w + wab * vab.w + wba * vba.w + wbb * vbb.w;
    ((float4*)g_sum)[gid] = o;
}

// lo-branch 4x4 windowed attention: reads g_sum (upsample) + fp32 g_qkv_lo,
// writes final split-fp16 sum.
__global__ void lo_attn_kernel()
{
    __shared__ __align__(16) float sm[2][4 * 1536];
    int wp = threadIdx.x >> 5;
    int lane = threadIdx.x & 31;
    int widx = blockIdx.x * 2 + wp;
    int b = widx >> 10, w = widx & 1023;

    const float4* src4 = (const float4*)(g_qkv_lo + (size_t)widx * 4 * 1536);
    float4* sm4 = (float4*)sm[wp];
    for (int f = lane; f < 1536; f += 32) sm4[f] = src4[f];
    __syncwarp();

    int h = lane >> 2, ti = lane & 3;
    const float* base = sm[wp];
    const float4* q4 = (const float4*)(base + ti * 1536 + h * 64);
    float s[4];
#pragma unroll
    for (int tj = 0; tj < 4; tj++) {
        const float4* k4 = (const float4*)(base + tj * 1536 + 512 + h * 64);
        float acc = 0.f;
#pragma unroll
        for (int d = 0; d < 16; d++) {
            float4 a = q4[d], kk = k4[d];
            acc += a.x * kk.x + a.y * kk.y + a.z * kk.z + a.w * kk.w;
        }
        s[tj] = acc * 0.125f;
    }
    float mx = fmaxf(fmaxf(s[0], s[1]), fmaxf(s[2], s[3]));
    float p[4], sum = 0.f;
#pragma unroll
    for (int tj = 0; tj < 4; tj++) { p[tj] = __expf(s[tj] - mx); sum += p[tj]; }
    float inv = 1.f / sum;
#pragma unroll
    for (int tj = 0; tj < 4; tj++) p[tj] *= inv;

    int wh = w >> 5, ww = w & 31;
    int nout = (wh * 2 + (ti >> 1)) * 64 + ww * 2 + (ti & 1);
    size_t obase = ((size_t)b * Ntok + nout) * Cch + h * 64;
    const float4* up4 = (const float4*)(g_sum + obase);
    const float4* v0 = (const float4*)(base + 0 * 1536 + 1024 + h * 64);
    const float4* v1 = (const float4*)(base + 1 * 1536 + 1024 + h * 64);
    const float4* v2 = (const float4*)(base + 2 * 1536 + 1024 + h * 64);
    const float4* v3 = (const float4*)(base + 3 * 1536 + 1024 + h * 64);
#pragma unroll
    for (int d = 0; d < 16; d++) {
        float4 o = up4[d];
        float4 a = v0[d], bb = v1[d], c = v2[d], e = v3[d];
        o.x += p[0] * a.x + p[1] * bb.x + p[2] * c.x + p[3] * e.x;
        o.y += p[0] * a.y + p[1] * bb.y + p[2] * c.y + p[3] * e.y;
        o.z += p[0] * a.z + p[1] * bb.z + p[2] * c.z + p[3] * e.z;
        o.w += p[0] * a.w + p[1] * bb.w + p[2] * c.w + p[3] * e.w;
        split4(o, g_sumh, g_suml, obase + d * 4);
    }
}

// ================= Launch =================
extern "C" void kernel_launch(void* const* d_in, const int* in_sizes, int n_in,
                              void* d_out, int out_size)
{
    const float* x = (const float*)d_in[0];
    const float* Wqkv = (const float*)d_in[1];
    const float* Wproj = (const float*)d_in[2];
    const float* bproj = (const float*)d_in[3];
    float* out = (float*)d_out;

    float *outhi, *qkvlo;
    fp16 *xhih, *xhil, *Wqh, *qh, *ql;
    fp16 *winh, *winl, *Wloh, *sumh, *suml, *Wph;
    cudaGetSymbolAddress((void**)&outhi, g_out_hi);
    cudaGetSymbolAddress((void**)&qkvlo, g_qkv_lo);
    cudaGetSymbolAddress((void**)&xhih, g_xhih);
    cudaGetSymbolAddress((void**)&xhil, g_xhil);
    cudaGetSymbolAddress((void**)&Wqh, g_Wqh);
    cudaGetSymbolAddress((void**)&qh, g_qh);
    cudaGetSymbolAddress((void**)&ql, g_ql);
    cudaGetSymbolAddress((void**)&winh, g_winh);
    cudaGetSymbolAddress((void**)&winl, g_winl);
    cudaGetSymbolAddress((void**)&Wloh, g_Wloh);
    cudaGetSymbolAddress((void**)&sumh, g_sumh);
    cudaGetSymbolAddress((void**)&suml, g_suml);
    cudaGetSymbolAddress((void**)&Wph, g_Wph);

    const int SMEM128 = 2 * (32768 + 128 * 128);  // 98304
    const int SMEMFA  = 32768 + 2 * 16384;        // 65536
    cudaFuncSetAttribute(mma_gemm<128, 0>, cudaFuncAttributeMaxDynamicSharedMemorySize, SMEM128);
    cudaFuncSetAttribute(mma_gemm<128, 1>, cudaFuncAttributeMaxDynamicSharedMemorySize, SMEM128);
    cudaFuncSetAttribute(mma_gemm<128, 2>, cudaFuncAttributeMaxDynamicSharedMemorySize, SMEM128);
    cudaFuncSetAttribute(flash_hi, cudaFuncAttributeMaxDynamicSharedMemorySize, SMEMFA);

    // input prep
    pool_split<<<4096, 256>>>(x);
    conv_single<<<768, 256>>>((const float4*)Wqkv, Wqh, 196608);
    gather_win_split<<<16384, 256>>>(x);
    permw_single<<<3072, 256>>>(Wqkv);
    conv_single<<<256, 256>>>((const float4*)Wproj, Wph, 65536);

    // qkv_hi = x_hi @ W_qkv^T : [8192 x 1536], K=512 -> split fp16 qh/ql
    mma_gemm<128, 2><<<dim3(12, 64, 1), 256, SMEM128>>>(
        xhih, xhil, 512, 0, 0, Wqh, 512, 0, 0,
        nullptr, qh, ql, 1536, 0, 0, nullptr, 512, 1.f, 1);

    // fused hi attention -> out_hi fp32
    flash_hi<<<dim3(8, 64), 128, SMEMFA>>>(qh, ql, outhi);

    upsample_kernel<<<16384, 256>>>();

    // qkv_lo = windows @ W_lo^T : [32768 x 1536], K=512 -> fp32
    mma_gemm<128, 0><<<dim3(12, 256, 1), 256, SMEM128>>>(
        winh, winl, 512, 0, 0, Wloh, 512, 0, 0,
        qkvlo, nullptr, nullptr, 1536, 0, 0, nullptr, 512, 1.f, 1);

    // lo attention + add upsample -> split fp16 sum
    lo_attn_kernel<<<4096, 64>>>();

    // out = sum @ W_proj^T + b : [32768 x 512], K=512
    mma_gemm<128, 1><<<dim3(4, 256, 1), 256, SMEM128>>>(
        sumh, suml, 512, 0, 0, Wph, 512, 0, 0,
        out, nullptr, nullptr, 512, 0, 0, bproj, 512, 1.f, 1);
}

// round 15
// speedup vs baseline: 1.4038x; 1.4038x over previous
#include <cuda_runtime.h>
#include <cuda_fp16.h>
#include <cstdint>
#include <math.h>

// ================= Problem constants =================
#define Bc 8
#define Ntok 4096
#define Cch 512
#define NHI 1024

typedef __half fp16;

// ================= Scratch =================
__device__ float g_out_hi[Bc * NHI * Cch];
__device__ float g_qkv_lo[(size_t)Bc * 1024 * 4 * 1536];
__device__ float g_sum[(size_t)Bc * Ntok * Cch];

__device__ fp16 g_xhih[Bc * NHI * Cch], g_xhil[Bc * NHI * Cch];
__device__ fp16 g_Wqh[1536 * 512];
__device__ fp16 g_qh[(size_t)Bc * NHI * 1536], g_ql[(size_t)Bc * NHI * 1536];
__device__ fp16 g_winh[(size_t)Bc * Ntok * Cch], g_winl[(size_t)Bc * Ntok * Cch];
__device__ fp16 g_Wloh[1536 * 512];
__device__ fp16 g_sumh[(size_t)Bc * Ntok * Cch], g_suml[(size_t)Bc * Ntok * Cch];
__device__ fp16 g_Wph[512 * 512];

// ================= helpers =================
__device__ __forceinline__ uint32_t smem_to_u32(const void* p) {
    uint32_t a;
    asm("{ .reg .u64 t; cvta.to.shared.u64 t, %1; cvt.u32.u64 %0, t; }" : "=r"(a) : "l"(p));
    return a;
}

__device__ __forceinline__ void cp16(uint32_t s, const void* g) {
    asm volatile("cp.async.cg.shared.global [%0], [%1], 16;" :: "r"(s), "l"(g) : "memory");
}
__device__ __forceinline__ void cp_commit() {
    asm volatile("cp.async.commit_group;" ::: "memory");
}
template <int N>
__device__ __forceinline__ void cp_wait() {
    asm volatile("cp.async.wait_group %0;" :: "n"(N) : "memory");
}

__device__ __forceinline__ void ldm4(uint32_t* r, uint32_t addr) {
    asm volatile("ldmatrix.sync.aligned.m8n8.x4.shared.b16 {%0,%1,%2,%3}, [%4];"
        : "=r"(r[0]), "=r"(r[1]), "=r"(r[2]), "=r"(r[3]) : "r"(addr));
}
__device__ __forceinline__ void ldm4t(uint32_t* r, uint32_t addr) {
    asm volatile("ldmatrix.sync.aligned.m8n8.x4.trans.shared.b16 {%0,%1,%2,%3}, [%4];"
        : "=r"(r[0]), "=r"(r[1]), "=r"(r[2]), "=r"(r[3]) : "r"(addr));
}

__device__ __forceinline__ void mma16816(float* c, const uint32_t* a, uint32_t b0, uint32_t b1) {
    asm volatile(
        "mma.sync.aligned.m16n8k16.row.col.f32.f16.f16.f32 "
        "{%0,%1,%2,%3}, {%4,%5,%6,%7}, {%8,%9}, {%0,%1,%2,%3};"
        : "+f"(c[0]), "+f"(c[1]), "+f"(c[2]), "+f"(c[3])
        : "r"(a[0]), "r"(a[1]), "r"(a[2]), "r"(a[3]), "r"(b0), "r"(b1));
}

__device__ __forceinline__ void psplit2(float x, float y, uint32_t& hp, uint32_t& lp) {
    fp16 hx = __float2half_rn(x), hy = __float2half_rn(y);
    fp16 lx = __float2half_rn(x - __half2float(hx));
    fp16 ly = __float2half_rn(y - __half2float(hy));
    hp = (uint32_t)*(uint16_t*)&hx | ((uint32_t)*(uint16_t*)&hy << 16);
    lp = (uint32_t)*(uint16_t*)&lx | ((uint32_t)*(uint16_t*)&ly << 16);
}

// ================= split-fp16 2-pass GEMM via mma.sync =================
// C = alpha * (Ah+Al) @ Bh^T (+bias). A split fp16, B single fp16.
// OUTMODE: 0 = fp32 C, 1 = fp32 C + bias, 2 = split fp16 (Ch, Cl)
// NOTE: launched with PADDED dynamic smem (131072) to pin occupancy to 1 CTA/SM
// (front-batched cp.async loops suffer cross-CTA L1tex-queue contention at occ>=2).
template <int NT, int OUTMODE>
__global__ void __launch_bounds__(NT == 128 ? 256 : 128) mma_gemm(
    const fp16* __restrict__ Ah, const fp16* __restrict__ Al, int lda, long long sAb, long long sAh,
    const fp16* __restrict__ Bh, int ldb, long long sBb, long long sBh,
    float* __restrict__ C, fp16* __restrict__ Ch, fp16* __restrict__ Cl,
    int ldc, long long sCb, long long sCh,
    const float* __restrict__ bias, int K, float alpha, int hdiv)
{
    constexpr int THREADS = (NT == 128) ? 256 : 128;
    constexpr int NWC = NT / 32;
    constexpr int BBYTES = NT * 128;
    constexpr int STAGE = 32768 + BBYTES;

    extern __shared__ __align__(1024) char smem[];
    uint32_t sb = smem_to_u32(smem);
    int tid = threadIdx.x, wid = tid >> 5, lane = tid & 31;
    int wr = wid / NWC, wc = wid % NWC;

    int z = blockIdx.z, zb = z / hdiv, zh = z - zb * hdiv;
    long long offA = zb * sAb + zh * sAh;
    long long offB = zb * sBb + zh * sBh;
    Ah += offA; Al += offA; Bh += offB;
    long long offC = zb * sCb + zh * sCh;
    int bm = blockIdx.y * 128, bn = blockIdx.x * NT;

    float acc[4][4][4];
#pragma unroll
    for (int i = 0; i < 4; i++)
#pragma unroll
        for (int j = 0; j < 4; j++)
#pragma unroll
            for (int t = 0; t < 4; t++) acc[i][j][t] = 0.f;

    int NC = K >> 6;

    auto issue = [&](int c) {
        int s = c & 1;
        int k0 = c * 64;
        uint32_t sbase = sb + s * STAGE;
#pragma unroll
        for (int i = 0; i < 1024 / THREADS; i++) {
            int idx = tid + i * THREADS;
            int row = idx >> 3, c16 = idx & 7;
            uint32_t d = (uint32_t)(row * 128 + ((c16 ^ (row & 7)) << 4));
            size_t go = (size_t)(bm + row) * lda + k0 + c16 * 8;
            cp16(sbase + d, Ah + go);
            cp16(sbase + 16384 + d, Al + go);
        }
#pragma unroll
        for (int i = 0; i < (NT * 8) / THREADS; i++) {
            int idx = tid + i * THREADS;
            int row = idx >> 3, c16 = idx & 7;
            uint32_t d = (uint32_t)(row * 128 + ((c16 ^ (row & 7)) << 4));
            size_t go = (size_t)(bn + row) * ldb + k0 + c16 * 8;
            cp16(sbase + 32768 + d, Bh + go);
        }
        cp_commit();
    };

    issue(0);

    for (int c = 0; c < NC; c++) {
        if (c + 1 < NC) { issue(c + 1); cp_wait<1>(); }
        else            { cp_wait<0>(); }
        __syncthreads();

        uint32_t Ab = sb + (c & 1) * STAGE;
        uint32_t Bb = Ab + 32768;
#pragma unroll
        for (int ks = 0; ks < 4; ks++) {
            uint32_t ah[4][4], al[4][4];
#pragma unroll
            for (int i = 0; i < 4; i++) {
                int row = wr * 64 + i * 16 + (lane & 15);
                int c16 = ks * 2 + (lane >> 4);
                uint32_t ad = (uint32_t)(row * 128 + ((c16 ^ (row & 7)) << 4));
                ldm4(ah[i], Ab + ad);
                ldm4(al[i], Ab + 16384 + ad);
            }
            uint32_t bh[8];
#pragma unroll
            for (int j2 = 0; j2 < 2; j2++) {
                int nrow = wc * 32 + j2 * 16 + ((lane >> 4) << 3) + (lane & 7);
                int c16 = ks * 2 + ((lane >> 3) & 1);
                uint32_t bd = (uint32_t)(nrow * 128 + ((c16 ^ (nrow & 7)) << 4));
                ldm4(&bh[j2 * 4], Bb + bd);
            }
#pragma unroll
            for (int i = 0; i < 4; i++)
#pragma unroll
                for (int j = 0; j < 4; j++) {
                    mma16816(acc[i][j], ah[i], bh[j * 2], bh[j * 2 + 1]);
                    mma16816(acc[i][j], al[i], bh[j * 2], bh[j * 2 + 1]);
                }
        }
        __syncthreads();
    }

    int r = lane >> 2, cp2 = (lane & 3) * 2;
#pragma unroll
    for (int i = 0; i < 4; i++) {
        int row = bm + wr * 64 + i * 16 + r;
#pragma unroll
        for (int j = 0; j < 4; j++) {
            int col = bn + wc * 32 + j * 8 + cp2;
            float2 v0, v1;
            v0.x = acc[i][j][0] * alpha; v0.y = acc[i][j][1] * alpha;
            v1.x = acc[i][j][2] * alpha; v1.y = acc[i][j][3] * alpha;
            if (OUTMODE == 1) {
                float b0 = bias[col], b1 = bias[col + 1];
                v0.x += b0; v0.y += b1; v1.x += b0; v1.y += b1;
            }
            if (OUTMODE == 2) {
                uint32_t hp, lp;
                psplit2(v0.x, v0.y, hp, lp);
                *(uint32_t*)&Ch[(offC + (size_t)row * ldc + col)] = hp;
                *(uint32_t*)&Cl[(offC + (size_t)row * ldc + col)] = lp;
                psplit2(v1.x, v1.y, hp, lp);
                *(uint32_t*)&Ch[(offC + (size_t)(row + 8) * ldc + col)] = hp;
                *(uint32_t*)&Cl[(offC + (size_t)(row + 8) * ldc + col)] = lp;
            } else {
                *(float2*)&C[offC + (size_t)row * ldc + col] = v0;
                *(float2*)&C[offC + (size_t)(row + 8) * ldc + col] = v1;
            }
        }
    }
}

// ================= FlashAttention-2 hi-branch (fp16 2-pass) =================
// Q split (qh/ql), K and V single fp16. out_hi fp32.
// Launched with padded smem (98304) -> occ 2 CTA/SM (matches R11 residency).
__global__ void __launch_bounds__(128) flash_hi(
    const fp16* __restrict__ Qh, const fp16* __restrict__ Ql, float* __restrict__ outhi)
{
    extern __shared__ __align__(1024) char smem[];
    uint32_t sb = smem_to_u32(smem);
    const uint32_t sQh = sb, sQl = sb + 16384;
    int tid = threadIdx.x, wid = tid >> 5, lane = tid & 31;
    int mtile = blockIdx.x, bh = blockIdx.y;
    int b = bh >> 3, h = bh & 7;

    size_t qbase = ((size_t)(b * 1024) + mtile * 128) * 1536 + h * 64;
#pragma unroll
    for (int i = 0; i < 8; i++) {
        int idx = tid + i * 128;
        int row = idx >> 3, c16 = idx & 7;
        uint32_t d = (uint32_t)(row * 128 + ((c16 ^ (row & 7)) << 4));
        size_t go = qbase + (size_t)row * 1536 + c16 * 8;
        cp16(sQh + d, Qh + go);
        cp16(sQl + d, Ql + go);
    }
    cp_commit();

    auto issueKV = [&](int t) {
        uint32_t kb = sb + 32768 + (t & 1) * 16384;
        size_t kbase = ((size_t)(b * 1024) + t * 64) * 1536 + 512 + h * 64;
#pragma unroll
        for (int i = 0; i < 4; i++) {
            int idx = tid + i * 128;
            int row = idx >> 3, c16 = idx & 7;
            uint32_t d = (uint32_t)(row * 128 + ((c16 ^ (row & 7)) << 4));
            size_t go = kbase + (size_t)row * 1536 + c16 * 8;
            cp16(kb + d, Qh + go);              // Kh
            cp16(kb + 8192 + d, Qh + go + 512); // Vh
        }
        cp_commit();
    };
    issueKV(0);
    issueKV(1);

    int rbase = wid * 32;
    float o[2][8][4];
    float mrow[2][2], lrow[2][2];
#pragma unroll
    for (int mi = 0; mi < 2; mi++) {
#pragma unroll
        for (int j = 0; j < 8; j++)
#pragma unroll
            for (int e = 0; e < 4; e++) o[mi][j][e] = 0.f;
        mrow[mi][0] = -INFINITY; mrow[mi][1] = -INFINITY;
        lrow[mi][0] = 0.f; lrow[mi][1] = 0.f;
    }

    for (int t = 0; t < 16; t++) {
        if (t < 15) cp_wait<1>(); else cp_wait<0>();
        __syncthreads();
        uint32_t kb = sb + 32768 + (t & 1) * 16384;

        float s[2][8][4];
#pragma unroll
        for (int mi = 0; mi < 2; mi++)
#pragma unroll
            for (int j = 0; j < 8; j++)
#pragma unroll
                for (int e = 0; e < 4; e++) s[mi][j][e] = 0.f;

#pragma unroll
        for (int kd = 0; kd < 4; kd++) {
            uint32_t aqh[2][4], aql[2][4];
#pragma unroll
            for (int mi = 0; mi < 2; mi++) {
                int row = rbase + mi * 16 + (lane & 15);
                int c16 = kd * 2 + (lane >> 4);
                uint32_t ad = (uint32_t)(row * 128 + ((c16 ^ (row & 7)) << 4));
                ldm4(aqh[mi], sQh + ad);
                ldm4(aql[mi], sQl + ad);
            }
            uint32_t bkh[16];
#pragma unroll
            for (int j2 = 0; j2 < 4; j2++) {
                int nrow = j2 * 16 + ((lane >> 4) << 3) + (lane & 7);
                int c16 = kd * 2 + ((lane >> 3) & 1);
                uint32_t bd = (uint32_t)(nrow * 128 + ((c16 ^ (nrow & 7)) << 4));
                ldm4(&bkh[j2 * 4], kb + bd);
            }
#pragma unroll
            for (int mi = 0; mi < 2; mi++)
#pragma unroll
                for (int j = 0; j < 8; j++) {
                    mma16816(s[mi][j], aqh[mi], bkh[j * 2], bkh[j * 2 + 1]);
                    mma16816(s[mi][j], aql[mi], bkh[j * 2], bkh[j * 2 + 1]);
                }
        }

#pragma unroll
        for (int mi = 0; mi < 2; mi++)
#pragma unroll
            for (int j = 0; j < 8; j++)
#pragma unroll
                for (int e = 0; e < 4; e++) s[mi][j][e] *= 0.125f;

#pragma unroll
        for (int mi = 0; mi < 2; mi++)
#pragma unroll
            for (int hf = 0; hf < 2; hf++) {
                float tm = -INFINITY;
#pragma unroll
                for (int j = 0; j < 8; j++)
                    tm = fmaxf(tm, fmaxf(s[mi][j][hf * 2], s[mi][j][hf * 2 + 1]));
                tm = fmaxf(tm, __shfl_xor_sync(0xffffffffu, tm, 1));
                tm = fmaxf(tm, __shfl_xor_sync(0xffffffffu, tm, 2));
                float mnew = fmaxf(mrow[mi][hf], tm);
                float corr = __expf(mrow[mi][hf] - mnew);
                mrow[mi][hf] = mnew;
                float rs = 0.f;
#pragma unroll
                for (int j = 0; j < 8; j++) {
                    float p0 = __expf(s[mi][j][hf * 2] - mnew);
                    float p1 = __expf(s[mi][j][hf * 2 + 1] - mnew);
                    s[mi][j][hf * 2] = p0; s[mi][j][hf * 2 + 1] = p1;
                    rs += p0 + p1;
                }
                rs += __shfl_xor_sync(0xffffffffu, rs, 1);
                rs += __shfl_xor_sync(0xffffffffu, rs, 2);
                lrow[mi][hf] = lrow[mi][hf] * corr + rs;
#pragma unroll
                for (int j = 0; j < 8; j++) {
                    o[mi][j][hf * 2] *= corr; o[mi][j][hf * 2 + 1] *= corr;
                }
            }

#pragma unroll
        for (int tt = 0; tt < 4; tt++) {
            uint32_t aph[2][4], apl[2][4];
#pragma unroll
            for (int mi = 0; mi < 2; mi++) {
                psplit2(s[mi][2 * tt][0], s[mi][2 * tt][1], aph[mi][0], apl[mi][0]);
                psplit2(s[mi][2 * tt][2], s[mi][2 * tt][3], aph[mi][1], apl[mi][1]);
                psplit2(s[mi][2 * tt + 1][0], s[mi][2 * tt + 1][1], aph[mi][2], apl[mi][2]);
                psplit2(s[mi][2 * tt + 1][2], s[mi][2 * tt + 1][3], aph[mi][3], apl[mi][3]);
            }
            uint32_t bvh[16];
#pragma unroll
            for (int j2 = 0; j2 < 4; j2++) {
                int vrow = tt * 16 + ((lane >> 3) & 1) * 8 + (lane & 7);
                int c16 = j2 * 2 + (lane >> 4);
                uint32_t vd = (uint32_t)(vrow * 128 + ((c16 ^ (vrow & 7)) << 4));
                ldm4t(&bvh[j2 * 4], kb + 8192 + vd);
            }
#pragma unroll
            for (int mi = 0; mi < 2; mi++)
#pragma unroll
                for (int j = 0; j < 8; j++) {
                    mma16816(o[mi][j], aph[mi], bvh[j * 2], bvh[j * 2 + 1]);
                    mma16816(o[mi][j], apl[mi], bvh[j * 2], bvh[j * 2 + 1]);
                }
        }
        __syncthreads();
        if (t + 2 < 16) issueKV(t + 2);
    }

    size_t obase = ((size_t)(b * 1024) + mtile * 128) * 512 + h * 64;
    int r = lane >> 2, c2 = (lane & 3) * 2;
#pragma unroll
    for (int mi = 0; mi < 2; mi++)
#pragma unroll
        for (int hf = 0; hf < 2; hf++) {
            float inv = 1.f / lrow[mi][hf];
            int grow = rbase + mi * 16 + hf * 8 + r;
#pragma unroll
            for (int j = 0; j < 8; j++) {
                float2 v;
                v.x = o[mi][j][hf * 2] * inv;
                v.y = o[mi][j][hf * 2 + 1] * inv;
                *(float2*)&outhi[obase + (size_t)grow * 512 + j * 8 + c2] = v;
            }
        }
}

// ================= prep kernels =================
__device__ __forceinline__ void split4(float4 v, fp16* h, fp16* l, size_t base)
{
    float a[4] = { v.x, v.y, v.z, v.w };
    fp16 hh[4], ll[4];
#pragma unroll
    for (int i = 0; i < 4; i++) {
        hh[i] = __float2half_rn(a[i]);
        ll[i] = __float2half_rn(a[i] - __half2float(hh[i]));
    }
    *(uint2*)(h + base) = *(uint2*)hh;
    *(uint2*)(l + base) = *(uint2*)ll;
}

// fp32 -> single fp16
__global__ void conv_single(const float4* __restrict__ src, fp16* __restrict__ h, int n4)
{
    int gid = blockIdx.x * 256 + threadIdx.x;
    if (gid >= n4) return;
    float4 v = src[gid];
    fp16 hh[4] = { __float2half_rn(v.x), __float2half_rn(v.y),
                   __float2half_rn(v.z), __float2half_rn(v.w) };
    *(uint2*)(h + (size_t)gid * 4) = *(uint2*)hh;
}

// ===== merged 2x2 pool + window gather (single pass over x) =====
// Each thread: one float4 channel-chunk of one 2x2 pixel group.
// Writes pooled split (g_xhih/l) + the 4 permuted window rows (g_winh/l).
__global__ void pool_gather_split(const float* __restrict__ x)
{
    int gid = blockIdx.x * 256 + threadIdx.x;   // B*1024*128
    int c4 = gid & 127;
    int hw = (gid >> 7) & 1023;
    int b = gid >> 17;
    int wh = hw >> 5, ww = hw & 31;
    int n0 = (wh * 2) * 64 + ww * 2;
    const float4* xb = (const float4*)(x + (size_t)b * Ntok * Cch);
    float4 v00 = xb[(size_t)n0 * 128 + c4];          // pixel (0,0) -> p=0
    float4 v01 = xb[(size_t)(n0 + 1) * 128 + c4];    // (0,1) -> p=1
    float4 v10 = xb[(size_t)(n0 + 64) * 128 + c4];   // (1,0) -> p=2
    float4 v11 = xb[(size_t)(n0 + 65) * 128 + c4];   // (1,1) -> p=3
    float4 o;
    o.x = (v00.x + v01.x + v10.x + v11.x) * 0.25f;
    o.y = (v00.y + v01.y + v10.y + v11.y) * 0.25f;
    o.z = (v00.z + v01.z + v10.z + v11.z) * 0.25f;
    o.w = (v00.w + v01.w + v10.w + v11.w) * 0.25f;
    split4(o, g_xhih, g_xhil, (size_t)gid * 4);

    int c = c4 * 4;
    int t = c >> 7, q = c & 127;
    size_t rowoff = (((size_t)(b * 1024 + hw)) * 4 + t) * 512;
    split4(v00, g_winh, g_winl, rowoff + 0 * 128 + q);
    split4(v01, g_winh, g_winl, rowoff + 1 * 128 + q);
    split4(v10, g_winh, g_winl, rowoff + 2 * 128 + q);
    split4(v11, g_winh, g_winl, rowoff + 3 * 128 + q);
}

__global__ void permw_single(const float* __restrict__ W)
{
    int gid = blockIdx.x * 256 + threadIdx.x;
    if (gid >= 1536 * 512) return;
    int kp = gid & 511, j = gid >> 9;
    int p = kp >> 7, q = kp & 127;
    g_Wloh[gid] = __float2half_rn(W[j * 512 + q * 4 + p]);
}

__device__ __forceinline__ void up_weights(int y, int& ia, int& ib, float& wa, float& wb)
{
    int m = y >> 1;
    if ((y & 1) == 0) { ia = m - 1 < 0 ? 0 : m - 1; ib = m; wa = 0.25f; wb = 0.75f; }
    else { ia = m; ib = m + 1 > 31 ? 31 : m + 1; wa = 0.75f; wb = 0.25f; }
}

__global__ void upsample_kernel()
{
    int gid = blockIdx.x * 256 + threadIdx.x;
    int c4 = gid & 127;
    int n = (gid >> 7) & 4095;
    int b = gid >> 19;
    int y = n >> 6, x = n & 63;
    int ya, yb2; float wya, wyb;
    int xa, xb2; float wxa, wxb;
    up_weights(y, ya, yb2, wya, wyb);
    up_weights(x, xa, xb2, wxa, wxb);
    const float4* src = (const float4*)(g_out_hi + (size_t)b * NHI * Cch);
    float4 vaa = src[(size_t)(ya * 32 + xa) * 128 + c4];
    float4 vab = src[(size_t)(ya * 32 + xb2) * 128 + c4];
    float4 vba = src[(size_t)(yb2 * 32 + xa) * 128 + c4];
    float4 vbb = src[(size_t)(yb2 * 32 + xb2) * 128 + c4];
    float waa = wya * wxa, wab = wya * wxb, wba = wyb * wxa, wbb = wyb * wxb;
    float4 o;
    o.x = waa * vaa.x + wab * vab.x + wba * vba.x + wbb * vbb.x;
    o.y = waa * vaa.y + wab * vab.y + wba * vba.y + wbb * vbb.y;
    o.z = waa * vaa.z + wab * vab.z + wba * vba.z + wbb * vbb.z;
    o.w = waa * vaa.w + wab * vab.w + wba * vba.w + wbb * vbb.w;
    ((float4*)g_sum)[gid] = o;
}

// lo-branch 4x4 windowed attention: reads g_sum (upsample) + fp32 g_qkv_lo,
// writes final split-fp16 sum.
__global__ void lo_attn_kernel()
{
    __shared__ __align__(16) float sm[2][4 * 1536];
    int wp = threadIdx.x >> 5;
    int lane = threadIdx.x & 31;
    int widx = blockIdx.x * 2 + wp;
    int b = widx >> 10, w = widx & 1023;

    const float4* src4 = (const float4*)(g_qkv_lo + (size_t)widx * 4 * 1536);
    float4* sm4 = (float4*)sm[wp];
    for (int f = lane; f < 1536; f += 32) sm4[f] = src4[f];
    __syncwarp();

    int h = lane >> 2, ti = lane & 3;
    const float* base = sm[wp];
    const float4* q4 = (const float4*)(base + ti * 1536 + h * 64);
    float s[4];
#pragma unroll
    for (int tj = 0; tj < 4; tj++) {
        const float4* k4 = (const float4*)(base + tj * 1536 + 512 + h * 64);
        float acc = 0.f;
#pragma unroll
        for (int d = 0; d < 16; d++) {
            float4 a = q4[d], kk = k4[d];
            acc += a.x * kk.x + a.y * kk.y + a.z * kk.z + a.w * kk.w;
        }
        s[tj] = acc * 0.125f;
    }
    float mx = fmaxf(fmaxf(s[0], s[1]), fmaxf(s[2], s[3]));
    float p[4], sum = 0.f;
#pragma unroll
    for (int tj = 0; tj < 4; tj++) { p[tj] = __expf(s[tj] - mx); sum += p[tj]; }
    float inv = 1.f / sum;
#pragma unroll
    for (int tj = 0; tj < 4; tj++) p[tj] *= inv;

    int wh = w >> 5, ww = w & 31;
    int nout = (wh * 2 + (ti >> 1)) * 64 + ww * 2 + (ti & 1);
    size_t obase = ((size_t)b * Ntok + nout) * Cch + h * 64;
    const float4* up4 = (const float4*)(g_sum + obase);
    const float4* v0 = (const float4*)(base + 0 * 1536 + 1024 + h * 64);
    const float4* v1 = (const float4*)(base + 1 * 1536 + 1024 + h * 64);
    const float4* v2 = (const float4*)(base + 2 * 1536 + 1024 + h * 64);
    const float4* v3 = (const float4*)(base + 3 * 1536 + 1024 + h * 64);
#pragma unroll
    for (int d = 0; d < 16; d++) {
        float4 o = up4[d];
        float4 a = v0[d], bb = v1[d], c = v2[d], e = v3[d];
        o.x += p[0] * a.x + p[1] * bb.x + p[2] * c.x + p[3] * e.x;
        o.y += p[0] * a.y + p[1] * bb.y + p[2] * c.y + p[3] * e.y;
        o.z += p[0] * a.z + p[1] * bb.z + p[2] * c.z + p[3] * e.z;
        o.w += p[0] * a.w + p[1] * bb.w + p[2] * c.w + p[3] * e.w;
        split4(o, g_sumh, g_suml, obase + d * 4);
    }
}

// ================= Launch =================
extern "C" void kernel_launch(void* const* d_in, const int* in_sizes, int n_in,
                              void* d_out, int out_size)
{
    const float* x = (const float*)d_in[0];
    const float* Wqkv = (const float*)d_in[1];
    const float* Wproj = (const float*)d_in[2];
    const float* bproj = (const float*)d_in[3];
    float* out = (float*)d_out;

    float *outhi, *qkvlo;
    fp16 *xhih, *xhil, *Wqh, *qh, *ql;
    fp16 *winh, *winl, *Wloh, *sumh, *suml, *Wph;
    cudaGetSymbolAddress((void**)&outhi, g_out_hi);
    cudaGetSymbolAddress((void**)&qkvlo, g_qkv_lo);
    cudaGetSymbolAddress((void**)&xhih, g_xhih);
    cudaGetSymbolAddress((void**)&xhil, g_xhil);
    cudaGetSymbolAddress((void**)&Wqh, g_Wqh);
    cudaGetSymbolAddress((void**)&qh, g_qh);
    cudaGetSymbolAddress((void**)&ql, g_ql);
    cudaGetSymbolAddress((void**)&winh, g_winh);
    cudaGetSymbolAddress((void**)&winl, g_winl);
    cudaGetSymbolAddress((void**)&Wloh, g_Wloh);
    cudaGetSymbolAddress((void**)&sumh, g_sumh);
    cudaGetSymbolAddress((void**)&suml, g_suml);
    cudaGetSymbolAddress((void**)&Wph, g_Wph);

    // PADDED smem requests to pin occupancy (kernels use less than requested):
    // mma_gemm uses 98304 -> request 131072 => 1 CTA/SM.
    // flash_hi uses 65536 -> request 98304  => 2 CTA/SM (R11 residency).
    const int SMEM_GEMM = 131072;
    const int SMEM_FA   = 98304;
    cudaFuncSetAttribute(mma_gemm<128, 0>, cudaFuncAttributeMaxDynamicSharedMemorySize, SMEM_GEMM);
    cudaFuncSetAttribute(mma_gemm<128, 1>, cudaFuncAttributeMaxDynamicSharedMemorySize, SMEM_GEMM);
    cudaFuncSetAttribute(mma_gemm<128, 2>, cudaFuncAttributeMaxDynamicSharedMemorySize, SMEM_GEMM);
    cudaFuncSetAttribute(flash_hi, cudaFuncAttributeMaxDynamicSharedMemorySize, SMEM_FA);

    // input prep (x read exactly once)
    pool_gather_split<<<4096, 256>>>(x);
    conv_single<<<768, 256>>>((const float4*)Wqkv, Wqh, 196608);
    permw_single<<<3072, 256>>>(Wqkv);
    conv_single<<<256, 256>>>((const float4*)Wproj, Wph, 65536);

    // qkv_hi = x_hi @ W_qkv^T : [8192 x 1536], K=512 -> split fp16 qh/ql
    mma_gemm<128, 2><<<dim3(12, 64, 1), 256, SMEM_GEMM>>>(
        xhih, xhil, 512, 0, 0, Wqh, 512, 0, 0,
        nullptr, qh, ql, 1536, 0, 0, nullptr, 512, 1.f, 1);

    // fused hi attention -> out_hi fp32
    flash_hi<<<dim3(8, 64), 128, SMEM_FA>>>(qh, ql, outhi);

    upsample_kernel<<<16384, 256>>>();

    // qkv_lo = windows @ W_lo^T : [32768 x 1536], K=512 -> fp32
    mma_gemm<128, 0><<<dim3(12, 256, 1), 256, SMEM_GEMM>>>(
        winh, winl, 512, 0, 0, Wloh, 512, 0, 0,
        qkvlo, nullptr, nullptr, 1536, 0, 0, nullptr, 512, 1.f, 1);

    // lo attention + add upsample -> split fp16 sum
    lo_attn_kernel<<<4096, 64>>>();

    // out = sum @ W_proj^T + b : [32768 x 512], K=512
    mma_gemm<128, 1><<<dim3(4, 256, 1), 256, SMEM_GEMM>>>(
        sumh, suml, 512, 0, 0, Wph, 512, 0, 0,
        out, nullptr, nullptr, 512, 0, 0, bproj, 512, 1.f, 1);
}